// round 10
// baseline (speedup 1.0000x reference)
#include <cuda_runtime.h>
#include <cuda_bf16.h>
#include <cstdint>

#define NG 256
#define NN 128
#define NT 16
#define NM 10
#define NE 1024
#define WSTRIDE 1792   // floats per warp buffer

typedef unsigned long long f2;

__device__ __forceinline__ f2 pack2(float a, float b) {
    f2 r; asm("mov.b64 %0,{%1,%2};" : "=l"(r) : "f"(a), "f"(b)); return r;
}
__device__ __forceinline__ void unpack2(f2 x, float &a, float &b) {
    asm("mov.b64 {%0,%1},%2;" : "=f"(a), "=f"(b) : "l"(x));
}
__device__ __forceinline__ f2 fma2_(f2 a, f2 b, f2 c) {
    f2 r; asm("fma.rn.f32x2 %0,%1,%2,%3;" : "=l"(r) : "l"(a), "l"(b), "l"(c)); return r;
}
__device__ __forceinline__ f2 mul2_(f2 a, f2 b) {
    f2 r; asm("mul.rn.f32x2 %0,%1,%2;" : "=l"(r) : "l"(a), "l"(b)); return r;
}
__device__ __forceinline__ f2 add2_(f2 a, f2 b) {
    f2 r; asm("add.rn.f32x2 %0,%1,%2;" : "=l"(r) : "l"(a), "l"(b)); return r;
}
__device__ __forceinline__ float hadd2_(f2 x) { float a, b; unpack2(x, a, b); return a + b; }

__device__ __forceinline__ void hmma(float* d, unsigned a0, unsigned a1, unsigned a2,
                                     unsigned a3, unsigned b0, unsigned b1) {
    asm volatile("mma.sync.aligned.m16n8k16.row.col.f32.bf16.bf16.f32 "
        "{%0,%1,%2,%3}, {%4,%5,%6,%7}, {%8,%9}, {%0,%1,%2,%3};"
        : "+f"(d[0]), "+f"(d[1]), "+f"(d[2]), "+f"(d[3])
        : "r"(a0), "r"(a1), "r"(a2), "r"(a3), "r"(b0), "r"(b1));
}
__device__ __forceinline__ unsigned bfp(unsigned p) {
    return ((p & 1u) ? 0x3F80u : 0u) | ((p & 2u) ? 0x3F800000u : 0u);
}

// smem carve (bytes): wbuf 4x7168 @0 | afrag 32768 @28672 | adjw 2048 @61440
// f1p @63488 | C2x2 @64000 | c2p @65600 | qsh @67200 | f2q @67360 | vsh @67520
#define SMEM_BYTES 67712

__global__ __launch_bounds__(128, 3)
void tgw_kernel(const int* __restrict__ ei, const float* __restrict__ tadj,
                const float* __restrict__ q0g, float* __restrict__ out)
{
    extern __shared__ __align__(16) unsigned char sraw[];
    float*    wbufA = (float*)sraw;
    uint4*    afrag = (uint4*)(sraw + 28672);
    unsigned* adjw  = (unsigned*)(sraw + 61440);
    float*    f1p   = (float*)(sraw + 63488);
    float*    C2x2A = (float*)(sraw + 64000);
    f2*       c2pA  = (f2*)(sraw + 65600);
    float*    qshA  = (float*)(sraw + 67200);
    float*    f2qA  = (float*)(sraw + 67360);
    float*    vshA  = (float*)(sraw + 67520);

    const int b    = blockIdx.x >> 2;
    const int w    = threadIdx.x >> 5;
    const int lane = threadIdx.x & 31;
    const int t    = ((blockIdx.x & 3) << 2) | w;
    const int lq   = lane >> 2;
    const int lr   = lane & 3;

    float* wbufw = wbufA + w * WSTRIDE;
    float* C2w   = C2x2A + w * 100;
    f2*    c2pw  = c2pA + w * 50;
    float* qshw  = qshA + w * NM;
    float* f2qw  = f2qA + w * NM;
    float* vshw  = vshA + w * 12;

    // ---- adjacency bitmask ----
    for (int i = threadIdx.x; i < NN * 4; i += 128) adjw[i] = 0u;
    __syncthreads();
    for (int e = threadIdx.x; e < NE; e += 128) {
        int ge = b * NE + e;
        int s = ei[ge] & (NN - 1);
        int d = ei[NG * NE + ge] & (NN - 1);
        atomicOr(&adjw[(s << 2) + (d >> 5)], 1u << (d & 31));
        atomicOr(&adjw[(d << 2) + (s >> 5)], 1u << (s & 31));
    }
    __syncthreads();
    {
        int i = threadIdx.x;
        int dg = __popc(adjw[i*4]) + __popc(adjw[i*4+1]) + __popc(adjw[i*4+2]) + __popc(adjw[i*4+3]);
        f1p[i] = (float)dg * (1.0f / NN);
    }

    // ---- A-fragment cache: C1 as m16n8k16 A frags, set s = mt*8+kt ----
    for (int s = w; s < 64; s += 4) {
        int mt = s >> 3, kt = s & 7;
        int i0 = 16 * mt + lq;
        int k0 = 16 * kt + 2 * lr;
        unsigned w0 = adjw[i0 * 4 + (k0 >> 5)] >> (k0 & 31);
        unsigned w1 = adjw[(i0 + 8) * 4 + (k0 >> 5)] >> (k0 & 31);
        afrag[s * 32 + lane] = make_uint4(bfp(w0 & 3u), bfp(w1 & 3u),
                                          bfp((w0 >> 8) & 3u), bfp((w1 >> 8) & 3u));
    }

    // ---- per-template constants ----
    const float* C2g = tadj + t * NM * NM;
    for (int idx = lane; idx < NM * NM; idx += 32) C2w[idx] = 2.0f * C2g[idx];
    __syncwarp();
    if (lane < NM) {
        float mx = -3.4e38f;
        #pragma unroll
        for (int j = 0; j < NM; ++j) mx = fmaxf(mx, q0g[t * NM + j]);
        float se = 0.f;
        #pragma unroll
        for (int j = 0; j < NM; ++j) se += __expf(q0g[t * NM + j] - mx);
        qshw[lane] = __expf(q0g[t * NM + lane] - mx) / se;
    }
    __syncwarp();
    if (lane < NM) {
        float acc = 0.f;
        #pragma unroll
        for (int j = 0; j < NM; ++j) { float c = C2g[lane * NM + j]; acc += c * c * qshw[j]; }
        f2qw[lane] = acc;
    }
    __syncwarp();
    for (int idx = lane; idx < NM * 5; idx += 32) {
        int m = idx / 5, jj = idx % 5;
        c2pw[idx] = pack2(C2w[(2 * jj) * NM + m], C2w[(2 * jj + 1) * NM + m]);
    }
    __syncthreads();

    // ---- per-warp registers ----
    float fi[4]; f2 fi2[4];
    #pragma unroll
    for (int r = 0; r < 4; ++r) { fi[r] = f1p[lane + 32 * r]; fi2[r] = pack2(fi[r], fi[r]); }
    f2 f2q2[5];
    #pragma unroll
    for (int mm = 0; mm < 5; ++mm) f2q2[mm] = *(const f2*)&f2qw[2 * mm];
    const float qmine = qshw[lane < NM ? lane : 0];

    // ---- K init from P0 = p q^T ----
    f2 K2[4][5];
    {
        f2 q2r[5];
        #pragma unroll
        for (int mm = 0; mm < 5; ++mm) q2r[mm] = *(const f2*)&qshw[2 * mm];
        float h0[NM];
        #pragma unroll
        for (int j = 0; j < NM; ++j) {
            const f2* cr = (const f2*)&C2w[j * NM];
            f2 a = mul2_(q2r[0], cr[0]);
            #pragma unroll
            for (int mm = 1; mm < 5; ++mm) a = fma2_(q2r[mm], cr[mm], a);
            h0[j] = hadd2_(a);
        }
        #pragma unroll
        for (int r = 0; r < 4; ++r)
            #pragma unroll
            for (int mm = 0; mm < 5; ++mm) {
                float t0 = fi[r] + f2qw[2*mm]   - fi[r] * h0[2*mm];
                float t1 = fi[r] + f2qw[2*mm+1] - fi[r] * h0[2*mm+1];
                K2[r][mm] = pack2(__expf(-20.f * t0), __expf(-20.f * t1));
            }
    }

    const f2 NEG1 = 0xBF800000BF800000ULL;
    f2 v2[5], uu2[4];
    float res = 0.f;
    float* redw = wbufw;

    #pragma unroll 1
    for (int outer = 0; outer < 5; ++outer) {
        #pragma unroll
        for (int mm = 0; mm < 5; ++mm) v2[mm] = 0x3F8000003F800000ULL;

        // ---- Sinkhorn x20 (warp-local) ----
        #pragma unroll 1
        for (int it = 0; it < 20; ++it) {
            #pragma unroll
            for (int r = 0; r < 4; ++r) {
                f2 a = mul2_(K2[r][0], v2[0]);
                #pragma unroll
                for (int mm = 1; mm < 5; ++mm) a = fma2_(K2[r][mm], v2[mm], a);
                float u = __fdividef(1.0f / NN, hadd2_(a));
                uu2[r] = pack2(u, u);
            }
            #pragma unroll
            for (int mm = 0; mm < 5; ++mm) {
                f2 a = mul2_(K2[0][mm], uu2[0]);
                #pragma unroll
                for (int r = 1; r < 4; ++r) a = fma2_(K2[r][mm], uu2[r], a);
                float pa, pb; unpack2(a, pa, pb);
                redw[(2*mm)*33 + lane]   = pa;
                redw[(2*mm+1)*33 + lane] = pb;
            }
            __syncwarp();
            {
                int j = lane % NM;
                int b0 = (lane >= NM) ? 16 : 0;
                const float* rj = &redw[j * 33];
                float a0 = rj[b0+0]+rj[b0+4]+rj[b0+8]+rj[b0+12];
                float a1 = rj[b0+1]+rj[b0+5]+rj[b0+9]+rj[b0+13];
                float a2 = rj[b0+2]+rj[b0+6]+rj[b0+10]+rj[b0+14];
                float a3 = rj[b0+3]+rj[b0+7]+rj[b0+11]+rj[b0+15];
                float sH = (a0 + a1) + (a2 + a3);
                float sO = __shfl_down_sync(0xFFFFFFFFu, sH, 10);
                if (lane < NM) vshw[lane] = __fdividef(qmine, sH + sO);
            }
            __syncwarp();
            #pragma unroll
            for (int mm = 0; mm < 5; ++mm) v2[mm] = *(const f2*)&vshw[2 * mm];
        }

        // ---- G = P*(2C2)^T ----
        #pragma unroll
        for (int r = 0; r < 4; ++r) {
            f2 w2[5]; f2 wb[10]; float gv[10];
            #pragma unroll
            for (int mm = 0; mm < 5; ++mm) {
                w2[mm] = mul2_(mul2_(K2[r][mm], v2[mm]), uu2[r]);
                float a, b2; unpack2(w2[mm], a, b2);
                wb[2*mm] = pack2(a, a); wb[2*mm+1] = pack2(b2, b2);
            }
            #pragma unroll
            for (int jj = 0; jj < 5; ++jj) {
                f2 a = mul2_(wb[0], c2pw[jj]);
                #pragma unroll
                for (int m = 1; m < NM; ++m) a = fma2_(wb[m], c2pw[m * 5 + jj], a);
                unpack2(a, gv[2*jj], gv[2*jj+1]);
            }
            int k = lane + 32 * r;
            if (outer < 4) {
                __nv_bfloat16* gh = (__nv_bfloat16*)wbufw;   // hi rows [j][136]; lo @+2176
                #pragma unroll
                for (int j = 0; j < NM; ++j) {
                    float g = gv[j];
                    __nv_bfloat16 h = __float2bfloat16(g);
                    __nv_bfloat16 l2 = __float2bfloat16(g - __bfloat162float(h));
                    gh[j * 136 + k] = h;
                    gh[2176 + j * 136 + k] = l2;
                }
            } else {
                f2* grow = (f2*)&wbufw[k * 14];
                #pragma unroll
                for (int jj = 0; jj < 5; ++jj) grow[jj] = pack2(gv[2*jj], gv[2*jj+1]);
            }
        }
        __syncwarp();

        if (outer < 4) {
            // ---- HMMA: cross = C1 * (G_hi + G_lo) ----
            const unsigned* gw = (const unsigned*)wbufw;   // 68 words/row; lo @+1088
            float acc[8][2][4];
            #pragma unroll
            for (int mt = 0; mt < 8; ++mt)
                #pragma unroll
                for (int nt = 0; nt < 2; ++nt) {
                    acc[mt][nt][0]=0.f; acc[mt][nt][1]=0.f; acc[mt][nt][2]=0.f; acc[mt][nt][3]=0.f;
                }
            const unsigned base0 = lq * 68 + lr;
            const unsigned base1 = (lq + 8) * 68 + lr;
            #pragma unroll 1
            for (int kt = 0; kt < 8; ++kt) {
                int o = kt * 8;
                unsigned bh00 = gw[base0+o],      bh01 = gw[base0+o+4];
                unsigned bh10 = gw[base1+o],      bh11 = gw[base1+o+4];
                unsigned bl00 = gw[base0+o+1088], bl01 = gw[base0+o+1092];
                unsigned bl10 = gw[base1+o+1088], bl11 = gw[base1+o+1092];
                const uint4* af = afrag + kt * 32 + lane;
                #pragma unroll
                for (int mt = 0; mt < 8; ++mt) {
                    uint4 a = af[mt * 256];
                    hmma(acc[mt][0], a.x, a.y, a.z, a.w, bh00, bh01);
                    hmma(acc[mt][1], a.x, a.y, a.z, a.w, bh10, bh11);
                    hmma(acc[mt][0], a.x, a.y, a.z, a.w, bl00, bl01);
                    hmma(acc[mt][1], a.x, a.y, a.z, a.w, bl10, bl11);
                }
            }
            // ---- store cross [128][14] then rebuild K ----
            float* cf = wbufw;
            #pragma unroll
            for (int mt = 0; mt < 8; ++mt)
                #pragma unroll
                for (int nt = 0; nt < 2; ++nt)
                    if (!(nt == 1 && lr == 3)) {           // cols 14,15 = pad
                        int col = 8 * nt + 2 * lr;
                        int i0 = 16 * mt + lq;
                        *(float2*)&cf[i0*14 + col]     = make_float2(acc[mt][nt][0], acc[mt][nt][1]);
                        *(float2*)&cf[(i0+8)*14 + col] = make_float2(acc[mt][nt][2], acc[mt][nt][3]);
                    }
            __syncwarp();
            #pragma unroll
            for (int r = 0; r < 4; ++r) {
                const f2* cr = (const f2*)&cf[(lane + 32 * r) * 14];
                #pragma unroll
                for (int mm = 0; mm < 5; ++mm) {
                    f2 base = add2_(fi2[r], f2q2[mm]);
                    f2 tens = fma2_(cr[mm], NEG1, base);
                    float t0, t1; unpack2(tens, t0, t1);
                    K2[r][mm] = pack2(__expf(-20.f * t0), __expf(-20.f * t1));
                }
            }
            __syncwarp();
        } else {
            // ---- final: sparse gather of G rows (stride 14); P from K2*u*v ----
            const uint4* adjv = (const uint4*)adjw;
            #pragma unroll 1
            for (int r = 0; r < 4; ++r) {
                uint4 aw = adjv[lane + 32 * r];
                f2 a0=0, a1=0, a2=0, a3=0, a4=0;
                #pragma unroll 1
                for (int wi = 0; wi < 4; ++wi) {
                    unsigned msk = (wi==0)?aw.x:(wi==1)?aw.y:(wi==2)?aw.z:aw.w;
                    while (msk) {
                        int kk = (wi << 5) + __ffs(msk) - 1;
                        msk &= msk - 1;
                        const f2* gk = (const f2*)&wbufw[kk * 14];
                        a0=add2_(a0,gk[0]); a1=add2_(a1,gk[1]); a2=add2_(a2,gk[2]);
                        a3=add2_(a3,gk[3]); a4=add2_(a4,gk[4]);
                    }
                }
                f2 accs[5] = {a0,a1,a2,a3,a4};
                f2 racc = 0;
                #pragma unroll
                for (int mm = 0; mm < 5; ++mm) {
                    f2 base = add2_(fi2[r], f2q2[mm]);
                    f2 tens = fma2_(accs[mm], NEG1, base);
                    f2 pij  = mul2_(mul2_(K2[r][mm], v2[mm]), uu2[r]);
                    racc = fma2_(tens, pij, racc);
                }
                res += hadd2_(racc);
            }
        }
    }

    #pragma unroll
    for (int off = 16; off; off >>= 1) res += __shfl_xor_sync(0xFFFFFFFFu, res, off);
    if (lane == 0) out[b * NT + t] = res;
}

extern "C" void kernel_launch(void* const* d_in, const int* in_sizes, int n_in,
                              void* d_out, int out_size) {
    const int* ei = nullptr; const float* tadj = nullptr; const float* q0 = nullptr;
    for (int i = 0; i < n_in; ++i) {
        if (in_sizes[i] == 2 * NG * NE) ei = (const int*)d_in[i];
        else if (in_sizes[i] == NT * NM * NM) tadj = (const float*)d_in[i];
        else if (in_sizes[i] == NT * NM) q0 = (const float*)d_in[i];
    }
    cudaFuncSetAttribute(tgw_kernel, cudaFuncAttributeMaxDynamicSharedMemorySize, SMEM_BYTES);
    tgw_kernel<<<NG * 4, 128, SMEM_BYTES>>>(ei, tadj, q0, (float*)d_out);
}

// round 14
// speedup vs baseline: 1.8200x; 1.8200x over previous
#include <cuda_runtime.h>
#include <cuda_bf16.h>
#include <cstdint>

#define NG 256
#define NN 128
#define NT 16
#define NM 10
#define NE 1024
#define WSTRIDE 1792

typedef unsigned long long f2;

__device__ __forceinline__ f2 pack2(float a, float b) {
    f2 r; asm("mov.b64 %0,{%1,%2};" : "=l"(r) : "f"(a), "f"(b)); return r;
}
__device__ __forceinline__ void unpack2(f2 x, float &a, float &b) {
    asm("mov.b64 {%0,%1},%2;" : "=f"(a), "=f"(b) : "l"(x));
}
__device__ __forceinline__ f2 fma2_(f2 a, f2 b, f2 c) {
    f2 r; asm("fma.rn.f32x2 %0,%1,%2,%3;" : "=l"(r) : "l"(a), "l"(b), "l"(c)); return r;
}
__device__ __forceinline__ f2 mul2_(f2 a, f2 b) {
    f2 r; asm("mul.rn.f32x2 %0,%1,%2;" : "=l"(r) : "l"(a), "l"(b)); return r;
}
__device__ __forceinline__ f2 add2_(f2 a, f2 b) {
    f2 r; asm("add.rn.f32x2 %0,%1,%2;" : "=l"(r) : "l"(a), "l"(b)); return r;
}
__device__ __forceinline__ float hadd2_(f2 x) { float a, b; unpack2(x, a, b); return a + b; }

__device__ __forceinline__ void hmma(float* d, unsigned a0, unsigned a1, unsigned a2,
                                     unsigned a3, unsigned b0, unsigned b1) {
    asm volatile("mma.sync.aligned.m16n8k16.row.col.f32.bf16.bf16.f32 "
        "{%0,%1,%2,%3}, {%4,%5,%6,%7}, {%8,%9}, {%0,%1,%2,%3};"
        : "+f"(d[0]), "+f"(d[1]), "+f"(d[2]), "+f"(d[3])
        : "r"(a0), "r"(a1), "r"(a2), "r"(a3), "r"(b0), "r"(b1));
}
__device__ __forceinline__ unsigned bfp(unsigned p) {
    return ((p & 1u) ? 0x3F80u : 0u) | ((p & 2u) ? 0x3F800000u : 0u);
}

// Sinkhorn 20 iterations, warp-local. Updates K-scaled u/v in uu2/v2.
#define SINKHORN20()                                                            \
    _Pragma("unroll")                                                           \
    for (int mm = 0; mm < 5; ++mm) v2[mm] = 0x3F8000003F800000ULL;              \
    _Pragma("unroll 1")                                                         \
    for (int it = 0; it < 20; ++it) {                                           \
        _Pragma("unroll")                                                       \
        for (int r = 0; r < 4; ++r) {                                           \
            f2 a = mul2_(K2[r][0], v2[0]);                                      \
            _Pragma("unroll")                                                   \
            for (int mm = 1; mm < 5; ++mm) a = fma2_(K2[r][mm], v2[mm], a);     \
            float u = __fdividef(1.0f / NN, hadd2_(a));                         \
            uu2[r] = pack2(u, u);                                               \
        }                                                                       \
        _Pragma("unroll")                                                       \
        for (int mm = 0; mm < 5; ++mm) {                                        \
            f2 a = mul2_(K2[0][mm], uu2[0]);                                    \
            _Pragma("unroll")                                                   \
            for (int r = 1; r < 4; ++r) a = fma2_(K2[r][mm], uu2[r], a);        \
            float pa, pb; unpack2(a, pa, pb);                                   \
            redw[(2*mm)*33 + lane]   = pa;                                      \
            redw[(2*mm+1)*33 + lane] = pb;                                      \
        }                                                                       \
        __syncwarp();                                                           \
        {                                                                       \
            int j = lane % NM;                                                  \
            int b0 = (lane >= NM) ? 16 : 0;                                     \
            const float* rj = &redw[j * 33];                                    \
            float a0 = rj[b0+0]+rj[b0+4]+rj[b0+8]+rj[b0+12];                    \
            float a1 = rj[b0+1]+rj[b0+5]+rj[b0+9]+rj[b0+13];                    \
            float a2 = rj[b0+2]+rj[b0+6]+rj[b0+10]+rj[b0+14];                   \
            float a3 = rj[b0+3]+rj[b0+7]+rj[b0+11]+rj[b0+15];                   \
            float sH = (a0 + a1) + (a2 + a3);                                   \
            float sO = __shfl_down_sync(0xFFFFFFFFu, sH, 10);                   \
            if (lane < NM) vshw[lane] = __fdividef(qmine, sH + sO);             \
        }                                                                       \
        __syncwarp();                                                           \
        _Pragma("unroll")                                                       \
        for (int mm = 0; mm < 5; ++mm) v2[mm] = *(const f2*)&vshw[2 * mm];      \
    }

// smem carve (bytes): wbuf 4x7168 @0 | afrag 32768 @28672 | adjw 2048 @61440
// f1p @63488 | C2x2 @64000 | c2p @65600 | qsh @67200 | f2q @67360 | vsh @67520
#define SMEM_BYTES 67712

__global__ __launch_bounds__(128, 3)
void tgw_kernel(const int* __restrict__ ei, const float* __restrict__ tadj,
                const float* __restrict__ q0g, float* __restrict__ out)
{
    extern __shared__ __align__(16) unsigned char sraw[];
    float*    wbufA = (float*)sraw;
    uint4*    afrag = (uint4*)(sraw + 28672);
    unsigned* adjw  = (unsigned*)(sraw + 61440);
    float*    f1p   = (float*)(sraw + 63488);
    float*    C2x2A = (float*)(sraw + 64000);
    f2*       c2pA  = (f2*)(sraw + 65600);
    float*    qshA  = (float*)(sraw + 67200);
    float*    f2qA  = (float*)(sraw + 67360);
    float*    vshA  = (float*)(sraw + 67520);

    const int b    = blockIdx.x >> 2;
    const int w    = threadIdx.x >> 5;
    const int lane = threadIdx.x & 31;
    const int t    = ((blockIdx.x & 3) << 2) | w;
    const int lq   = lane >> 2;
    const int lr   = lane & 3;

    float* wbufw = wbufA + w * WSTRIDE;
    float* C2w   = C2x2A + w * 100;
    f2*    c2pw  = c2pA + w * 50;
    float* qshw  = qshA + w * NM;
    float* f2qw  = f2qA + w * NM;
    float* vshw  = vshA + w * 12;

    // ---- adjacency bitmask ----
    for (int i = threadIdx.x; i < NN * 4; i += 128) adjw[i] = 0u;
    __syncthreads();
    for (int e = threadIdx.x; e < NE; e += 128) {
        int ge = b * NE + e;
        int s = ei[ge] & (NN - 1);
        int d = ei[NG * NE + ge] & (NN - 1);
        atomicOr(&adjw[(s << 2) + (d >> 5)], 1u << (d & 31));
        atomicOr(&adjw[(d << 2) + (s >> 5)], 1u << (s & 31));
    }
    __syncthreads();
    {
        int i = threadIdx.x;
        int dg = __popc(adjw[i*4]) + __popc(adjw[i*4+1]) + __popc(adjw[i*4+2]) + __popc(adjw[i*4+3]);
        f1p[i] = (float)dg * (1.0f / NN);
    }

    // ---- A-fragment cache: C1 as m16n8k16 A frags ----
    for (int s = w; s < 64; s += 4) {
        int mt = s >> 3, kt = s & 7;
        int i0 = 16 * mt + lq;
        int k0 = 16 * kt + 2 * lr;
        unsigned w0 = adjw[i0 * 4 + (k0 >> 5)] >> (k0 & 31);
        unsigned w1 = adjw[(i0 + 8) * 4 + (k0 >> 5)] >> (k0 & 31);
        afrag[s * 32 + lane] = make_uint4(bfp(w0 & 3u), bfp(w1 & 3u),
                                          bfp((w0 >> 8) & 3u), bfp((w1 >> 8) & 3u));
    }

    // ---- per-template constants ----
    const float* C2g = tadj + t * NM * NM;
    for (int idx = lane; idx < NM * NM; idx += 32) C2w[idx] = 2.0f * C2g[idx];
    __syncwarp();
    if (lane < NM) {
        float mx = -3.4e38f;
        #pragma unroll
        for (int j = 0; j < NM; ++j) mx = fmaxf(mx, q0g[t * NM + j]);
        float se = 0.f;
        #pragma unroll
        for (int j = 0; j < NM; ++j) se += __expf(q0g[t * NM + j] - mx);
        qshw[lane] = __expf(q0g[t * NM + lane] - mx) / se;
    }
    __syncwarp();
    if (lane < NM) {
        float acc = 0.f;
        #pragma unroll
        for (int j = 0; j < NM; ++j) { float c = C2g[lane * NM + j]; acc += c * c * qshw[j]; }
        f2qw[lane] = acc;
    }
    __syncwarp();
    for (int idx = lane; idx < NM * 5; idx += 32) {
        int m = idx / 5, jj = idx % 5;
        c2pw[idx] = pack2(C2w[(2 * jj) * NM + m], C2w[(2 * jj + 1) * NM + m]);
    }
    __syncthreads();

    // ---- per-warp registers ----
    float fi[4]; f2 fi2[4];
    #pragma unroll
    for (int r = 0; r < 4; ++r) { fi[r] = f1p[lane + 32 * r]; fi2[r] = pack2(fi[r], fi[r]); }
    f2 f2q2[5];
    #pragma unroll
    for (int mm = 0; mm < 5; ++mm) f2q2[mm] = *(const f2*)&f2qw[2 * mm];
    const float qmine = qshw[lane < NM ? lane : 0];

    // ---- K init from P0 = p q^T ----
    f2 K2[4][5];
    {
        f2 q2r[5];
        #pragma unroll
        for (int mm = 0; mm < 5; ++mm) q2r[mm] = *(const f2*)&qshw[2 * mm];
        float h0[NM];
        #pragma unroll
        for (int j = 0; j < NM; ++j) {
            const f2* cr = (const f2*)&C2w[j * NM];
            f2 a = mul2_(q2r[0], cr[0]);
            #pragma unroll
            for (int mm = 1; mm < 5; ++mm) a = fma2_(q2r[mm], cr[mm], a);
            h0[j] = hadd2_(a);
        }
        #pragma unroll
        for (int r = 0; r < 4; ++r)
            #pragma unroll
            for (int mm = 0; mm < 5; ++mm) {
                float t0 = fi[r] + f2qw[2*mm]   - fi[r] * h0[2*mm];
                float t1 = fi[r] + f2qw[2*mm+1] - fi[r] * h0[2*mm+1];
                K2[r][mm] = pack2(__expf(-20.f * t0), __expf(-20.f * t1));
            }
    }

    const f2 NEG1 = 0xBF800000BF800000ULL;
    f2 v2[5], uu2[4];
    float res = 0.f;
    float* redw = wbufw;

    // ============ steady-state outers 0..3: Sinkhorn -> G(bf16) -> HMMA -> K ============
    #pragma unroll 1
    for (int outer = 0; outer < 4; ++outer) {
        SINKHORN20();

        // G = P*(2C2)^T, bf16 hi/lo split: hi rows [j][136]; lo @+2176 (bf16 elems)
        #pragma unroll
        for (int r = 0; r < 4; ++r) {
            f2 w2[5]; f2 wb[10]; float gv[10];
            #pragma unroll
            for (int mm = 0; mm < 5; ++mm) {
                w2[mm] = mul2_(mul2_(K2[r][mm], v2[mm]), uu2[r]);
                float a, b2; unpack2(w2[mm], a, b2);
                wb[2*mm] = pack2(a, a); wb[2*mm+1] = pack2(b2, b2);
            }
            #pragma unroll
            for (int jj = 0; jj < 5; ++jj) {
                f2 a = mul2_(wb[0], c2pw[jj]);
                #pragma unroll
                for (int m = 1; m < NM; ++m) a = fma2_(wb[m], c2pw[m * 5 + jj], a);
                unpack2(a, gv[2*jj], gv[2*jj+1]);
            }
            int k = lane + 32 * r;
            __nv_bfloat16* gh = (__nv_bfloat16*)wbufw;
            #pragma unroll
            for (int j = 0; j < NM; ++j) {
                float g = gv[j];
                __nv_bfloat16 h = __float2bfloat16(g);
                __nv_bfloat16 l2 = __float2bfloat16(g - __bfloat162float(h));
                gh[j * 136 + k] = h;
                gh[2176 + j * 136 + k] = l2;
            }
        }
        __syncwarp();

        // HMMA: cross = C1 * (G_hi + G_lo)
        {
            const unsigned* gw = (const unsigned*)wbufw;   // 68 words/row; lo @+1088
            float acc[8][2][4];
            #pragma unroll
            for (int mt = 0; mt < 8; ++mt)
                #pragma unroll
                for (int nt = 0; nt < 2; ++nt) {
                    acc[mt][nt][0]=0.f; acc[mt][nt][1]=0.f; acc[mt][nt][2]=0.f; acc[mt][nt][3]=0.f;
                }
            const unsigned base0 = lq * 68 + lr;
            const unsigned base1 = (lq + 8) * 68 + lr;
            #pragma unroll 1
            for (int kt = 0; kt < 8; ++kt) {
                int o = kt * 8;
                unsigned bh00 = gw[base0+o],      bh01 = gw[base0+o+4];
                unsigned bh10 = gw[base1+o],      bh11 = gw[base1+o+4];
                unsigned bl00 = gw[base0+o+1088], bl01 = gw[base0+o+1092];
                unsigned bl10 = gw[base1+o+1088], bl11 = gw[base1+o+1092];
                const uint4* af = afrag + kt * 32 + lane;
                #pragma unroll
                for (int mt = 0; mt < 8; ++mt) {
                    uint4 a = af[mt * 256];
                    hmma(acc[mt][0], a.x, a.y, a.z, a.w, bh00, bh01);
                    hmma(acc[mt][1], a.x, a.y, a.z, a.w, bh10, bh11);
                    hmma(acc[mt][0], a.x, a.y, a.z, a.w, bl00, bl01);
                    hmma(acc[mt][1], a.x, a.y, a.z, a.w, bl10, bl11);
                }
            }
            float* cf = wbufw;                             // cross [128][14]
            #pragma unroll
            for (int mt = 0; mt < 8; ++mt)
                #pragma unroll
                for (int nt = 0; nt < 2; ++nt)
                    if (!(nt == 1 && lr == 3)) {
                        int col = 8 * nt + 2 * lr;
                        int i0 = 16 * mt + lq;
                        *(float2*)&cf[i0*14 + col]     = make_float2(acc[mt][nt][0], acc[mt][nt][1]);
                        *(float2*)&cf[(i0+8)*14 + col] = make_float2(acc[mt][nt][2], acc[mt][nt][3]);
                    }
        }
        __syncwarp();
        #pragma unroll
        for (int r = 0; r < 4; ++r) {
            const f2* cr = (const f2*)&wbufw[(lane + 32 * r) * 14];
            #pragma unroll
            for (int mm = 0; mm < 5; ++mm) {
                f2 base = add2_(fi2[r], f2q2[mm]);
                f2 tens = fma2_(cr[mm], NEG1, base);
                float t0, t1; unpack2(tens, t0, t1);
                K2[r][mm] = pack2(__expf(-20.f * t0), __expf(-20.f * t1));
            }
        }
        __syncwarp();
    }

    // ============ peeled final outer: Sinkhorn -> G(f32) -> sparse gather ============
    {
        SINKHORN20();

        #pragma unroll
        for (int r = 0; r < 4; ++r) {
            f2 w2[5]; f2 wb[10]; float gv[10];
            #pragma unroll
            for (int mm = 0; mm < 5; ++mm) {
                w2[mm] = mul2_(mul2_(K2[r][mm], v2[mm]), uu2[r]);
                float a, b2; unpack2(w2[mm], a, b2);
                wb[2*mm] = pack2(a, a); wb[2*mm+1] = pack2(b2, b2);
            }
            #pragma unroll
            for (int jj = 0; jj < 5; ++jj) {
                f2 a = mul2_(wb[0], c2pw[jj]);
                #pragma unroll
                for (int m = 1; m < NM; ++m) a = fma2_(wb[m], c2pw[m * 5 + jj], a);
                unpack2(a, gv[2*jj], gv[2*jj+1]);
            }
            int k = lane + 32 * r;
            f2* grow = (f2*)&wbufw[k * 14];
            #pragma unroll
            for (int jj = 0; jj < 5; ++jj) grow[jj] = pack2(gv[2*jj], gv[2*jj+1]);
        }
        __syncwarp();

        const uint4* adjv = (const uint4*)adjw;
        #pragma unroll 1
        for (int r = 0; r < 4; ++r) {
            uint4 aw = adjv[lane + 32 * r];
            f2 a0=0, a1=0, a2=0, a3=0, a4=0;
            #pragma unroll 1
            for (int wi = 0; wi < 4; ++wi) {
                unsigned msk = (wi==0)?aw.x:(wi==1)?aw.y:(wi==2)?aw.z:aw.w;
                while (msk) {
                    int kk = (wi << 5) + __ffs(msk) - 1;
                    msk &= msk - 1;
                    const f2* gk = (const f2*)&wbufw[kk * 14];
                    a0=add2_(a0,gk[0]); a1=add2_(a1,gk[1]); a2=add2_(a2,gk[2]);
                    a3=add2_(a3,gk[3]); a4=add2_(a4,gk[4]);
                }
            }
            f2 accs[5] = {a0,a1,a2,a3,a4};
            f2 racc = 0;
            #pragma unroll
            for (int mm = 0; mm < 5; ++mm) {
                f2 base = add2_(fi2[r], f2q2[mm]);
                f2 tens = fma2_(accs[mm], NEG1, base);
                f2 pij  = mul2_(mul2_(K2[r][mm], v2[mm]), uu2[r]);
                racc = fma2_(tens, pij, racc);
            }
            res += hadd2_(racc);
        }
    }

    #pragma unroll
    for (int off = 16; off; off >>= 1) res += __shfl_xor_sync(0xFFFFFFFFu, res, off);
    if (lane == 0) out[b * NT + t] = res;
}

extern "C" void kernel_launch(void* const* d_in, const int* in_sizes, int n_in,
                              void* d_out, int out_size) {
    const int* ei = nullptr; const float* tadj = nullptr; const float* q0 = nullptr;
    for (int i = 0; i < n_in; ++i) {
        if (in_sizes[i] == 2 * NG * NE) ei = (const int*)d_in[i];
        else if (in_sizes[i] == NT * NM * NM) tadj = (const float*)d_in[i];
        else if (in_sizes[i] == NT * NM) q0 = (const float*)d_in[i];
    }
    cudaFuncSetAttribute(tgw_kernel, cudaFuncAttributeMaxDynamicSharedMemorySize, SMEM_BYTES);
    tgw_kernel<<<NG * 4, 128, SMEM_BYTES>>>(ei, tadj, q0, (float*)d_out);
}